// round 15
// baseline (speedup 1.0000x reference)
#include <cuda_runtime.h>
#include <cuda_fp16.h>
#include <cstdint>

#define NPTS    16384
#define NBINS   256
#define NSLICE  16
#define SLICEN  (NPTS/NSLICE)      // 1024 targets per slice
#define SQUART  4
#define SEEDN   (SLICEN/SQUART)    // 256 targets per seed unit
#define TPB     256                // prep/reduction block size
#define TPBS    512                // seed/sweep block size (16 warps)
#define QPB2    512                // queries per seed/sweep block
#define QT2     (NPTS/QPB2)        // 32 query tiles per direction
#define REDB    (2*NPTS/TPB)       // 128
#define XLO     (-8.0f)
#define XWIDTH  (16.0f/NBINS)

__device__ int      g_hist[2][NBINS];
__device__ int      g_start[2][NBINS + 1];
__device__ int      g_cursor[2][NBINS];
__device__ unsigned g_exlo[2][NSLICE], g_exhi[2][NSLICE];
__device__ float4   g_pts[2][NPTS];          // sorted (x,y,z, orig_idx bits)
__device__ uint4    g_frag[2][NPTS][2];      // target B-fragments, sorted order
__device__ uint4    g_qA[2][NPTS][2];        // query A-fragments, sorted order
__device__ float2   g_qmeta[2][NPTS];        // (qsq, orig_idx bits), sorted order
__device__ unsigned g_best[2][NPTS];         // per-row best (encoded), atomicMin
__device__ float    g_bsum[REDB];
__device__ unsigned g_ticket;

static __device__ __forceinline__ unsigned enc_f(float f) {
    unsigned u = __float_as_uint(f);
    return (u & 0x80000000u) ? ~u : (u | 0x80000000u);
}
static __device__ __forceinline__ float dec_f(unsigned u) {
    unsigned b = (u & 0x80000000u) ? (u & 0x7fffffffu) : ~u;
    return __uint_as_float(b);
}
static __device__ __forceinline__ unsigned pkh2(__half lo, __half hi) {
    __half2 h = __halves2half2(lo, hi);
    return *reinterpret_cast<unsigned*>(&h);
}

// m16n8k16 fp16 MMA, fp32 accumulate. A row-major, B col-major.
#define MMA_F16(d0,d1,d2,d3, a0,a1,a2,a3, b0,b1, c0,c1,c2,c3)                       \
    asm("mma.sync.aligned.m16n8k16.row.col.f32.f16.f16.f32 "                        \
        "{%0,%1,%2,%3}, {%4,%5,%6,%7}, {%8,%9}, {%10,%11,%12,%13};"                 \
        : "=f"(d0), "=f"(d1), "=f"(d2), "=f"(d3)                                    \
        : "r"(a0), "r"(a1), "r"(a2), "r"(a3), "r"(b0), "r"(b1),                     \
          "f"(c0), "f"(c1), "f"(c2), "f"(c3))

// ============================================================================
// 1) x-histogram + per-row best init
// ============================================================================
__global__ void k_hist(const float* __restrict__ adv, const float* __restrict__ ori) {
    int i = blockIdx.x * blockDim.x + threadIdx.x;
    int c = i >> 14, idx = i & (NPTS - 1);
    const float* src = c ? ori : adv;
    float x = src[3 * idx];
    int bin = min(max((int)((x - XLO) * (1.0f / XWIDTH)), 0), NBINS - 1);
    atomicAdd(&g_hist[c][bin], 1);
    g_best[c][idx] = 0xFF800000u;   // enc(+inf)
}

// ============================================================================
// 2) prefix-sum; zero hist/cursor; init slice-range accumulators.
// ============================================================================
__global__ void k_scan() {
    int lane = threadIdx.x & 31;
    int c    = threadIdx.x >> 5;
    int h[8], s8 = 0;
#pragma unroll
    for (int k = 0; k < 8; k++) { h[k] = g_hist[c][lane * 8 + k]; s8 += h[k]; }
    int incl = s8;
#pragma unroll
    for (int off = 1; off < 32; off <<= 1) {
        int v = __shfl_up_sync(0xffffffffu, incl, off);
        if (lane >= off) incl += v;
    }
    int run = incl - s8;
#pragma unroll
    for (int k = 0; k < 8; k++) { g_start[c][lane * 8 + k] = run; run += h[k]; }
    if (lane == 31) g_start[c][NBINS] = run;
#pragma unroll
    for (int k = 0; k < 8; k++) {
        g_hist[c][lane * 8 + k]   = 0;
        g_cursor[c][lane * 8 + k] = 0;
    }
    if (lane < NSLICE) { g_exlo[c][lane] = 0xFFFFFFFFu; g_exhi[c][lane] = 0u; }
}

// ============================================================================
// 3) counting-sort scatter: sorted points + target-B and query-A fragment
//    tables + query meta + exact slice x-ranges.
// ============================================================================
__global__ void k_scatter(const float* __restrict__ adv, const float* __restrict__ ori) {
    int i = blockIdx.x * blockDim.x + threadIdx.x;
    int c = i >> 14, idx = i & (NPTS - 1);
    const float* src = c ? ori : adv;
    float x = src[3 * idx], y = src[3 * idx + 1], z = src[3 * idx + 2];
    int bin = min(max((int)((x - XLO) * (1.0f / XWIDTH)), 0), NBINS - 1);
    int pos = g_start[c][bin] + atomicAdd(&g_cursor[c][bin], 1);

    g_pts[c][pos] = make_float4(x, y, z, __int_as_float(idx));
    int s = pos >> 10;              // pos / SLICEN
    unsigned ex = enc_f(x);
    atomicMin(&g_exlo[c][s], ex);
    atomicMax(&g_exhi[c][s], ex);

    __half xh = __float2half_rn(x), yh = __float2half_rn(y), zh = __float2half_rn(z);
    __half xl = __float2half_rn(x - __half2float(xh));
    __half yl = __float2half_rn(y - __half2float(yh));
    __half zl = __float2half_rn(z - __half2float(zh));
    float sq = x * x + y * y + z * z;
    __half one = __float2half_rn(1.f), hz = __float2half_rn(0.f);

    float tq = -0.5f * sq;
    __half tqh = __float2half_rn(tq);
    __half tql = __float2half_rn(tq - __half2float(tqh));
    g_frag[c][pos][0] = make_uint4(pkh2(xh, yh), pkh2(zl, tqh), pkh2(zh, xh), pkh2(tql, hz));
    g_frag[c][pos][1] = make_uint4(pkh2(yh, zh), 0u, pkh2(xl, yl), 0u);

    g_qA[c][pos][0] = make_uint4(pkh2(xh, yh), pkh2(zh, one), pkh2(zh, xl), pkh2(one, hz));
    g_qA[c][pos][1] = make_uint4(pkh2(yl, zl), 0u, pkh2(xh, yh), 0u);
    g_qmeta[c][pos] = make_float2(sq, __int_as_float(idx));
}

// ---- MMA sweep over TN staged targets; A-fragments direct from g_qA ----
static __device__ __forceinline__ void sweep_and_commit(
    const uint2* sb, int TN, int qc, int dir, int qbase, int tid) {
    int lane = tid & 31, warp = tid >> 5;
    int gid = lane >> 2, tl = lane & 3;
    int r0 = qbase + warp * 32 + gid;
    const uint2* qa = reinterpret_cast<const uint2*>(&g_qA[qc][0][0]);
    uint2 u0 = __ldg(&qa[(r0 +  0) * 4 + tl]);
    uint2 u1 = __ldg(&qa[(r0 +  8) * 4 + tl]);
    uint2 u2 = __ldg(&qa[(r0 + 16) * 4 + tl]);
    uint2 u3 = __ldg(&qa[(r0 + 24) * 4 + tl]);

    float ninf = __int_as_float(0xFF800000);
    float mx00 = ninf, mx01 = ninf, mx10 = ninf, mx11 = ninf;
    const float zf = 0.0f;
#pragma unroll 4
    for (int j = 0; j < TN; j += 8) {
        uint2 bb = sb[(j + gid) * 4 + tl];
        float d0, d1, d2, d3;
        MMA_F16(d0, d1, d2, d3, u0.x, u1.x, u0.y, u1.y, bb.x, bb.y, zf, zf, zf, zf);
        mx00 = fmaxf(mx00, fmaxf(d0, d1));
        mx01 = fmaxf(mx01, fmaxf(d2, d3));
        MMA_F16(d0, d1, d2, d3, u2.x, u3.x, u2.y, u3.y, bb.x, bb.y, zf, zf, zf, zf);
        mx10 = fmaxf(mx10, fmaxf(d0, d1));
        mx11 = fmaxf(mx11, fmaxf(d2, d3));
    }
#pragma unroll
    for (int off = 1; off <= 2; off <<= 1) {
        mx00 = fmaxf(mx00, __shfl_xor_sync(0xffffffffu, mx00, off));
        mx01 = fmaxf(mx01, __shfl_xor_sync(0xffffffffu, mx01, off));
        mx10 = fmaxf(mx10, __shfl_xor_sync(0xffffffffu, mx10, off));
        mx11 = fmaxf(mx11, __shfl_xor_sync(0xffffffffu, mx11, off));
    }
    if (tl == 0) {
        float2 m0 = g_qmeta[qc][r0 +  0];
        float2 m1 = g_qmeta[qc][r0 +  8];
        float2 m2 = g_qmeta[qc][r0 + 16];
        float2 m3 = g_qmeta[qc][r0 + 24];
        atomicMin(&g_best[dir][__float_as_int(m0.y)], enc_f(fmaf(-2.f, mx00, m0.x)));
        atomicMin(&g_best[dir][__float_as_int(m1.y)], enc_f(fmaf(-2.f, mx01, m1.x)));
        atomicMin(&g_best[dir][__float_as_int(m2.y)], enc_f(fmaf(-2.f, mx10, m2.x)));
        atomicMin(&g_best[dir][__float_as_int(m3.y)], enc_f(fmaf(-2.f, mx11, m3.x)));
    }
}

// ============================================================================
// 4) seed: block = (dir, 512-query tile, quarter of home slice). 512 threads;
//    131K cells/block for 2x better fixed-cost amortization.
// ============================================================================
__global__ void __launch_bounds__(TPBS)
k_seed() {
    __shared__ uint4 sB4[SEEDN * 2];    // 8 KB

    int b = blockIdx.x;
    int dir = b / (QT2 * SQUART);
    int rem = b % (QT2 * SQUART);
    int qt = rem / SQUART, qu = rem % SQUART;
    int qc = dir, tc = 1 - dir;
    int tid = threadIdx.x;
    int tb = (qt >> 1) * SLICEN + qu * SEEDN;   // home slice of this 512-query tile

    for (int k = tid; k < SEEDN * 2; k += TPBS) sB4[k] = g_frag[tc][tb + (k >> 1)][k & 1];
    __syncthreads();
    sweep_and_commit(reinterpret_cast<const uint2*>(sB4), SEEDN,
                     qc, dir, qt * QPB2, tid);
}

// ============================================================================
// 5) sweep: block = (dir, 512-query tile, slice). Per-warp tight bound from
//    g_best; survivors stage 32KB once for 512 queries.
// ============================================================================
__global__ void __launch_bounds__(TPBS)
k_sweep() {
    __shared__ uint4 sB4[SLICEN * 2];   // 32 KB

    int b = blockIdx.x;
    int dir = b / (QT2 * NSLICE);
    int rem = b % (QT2 * NSLICE);
    int qt = rem / NSLICE, sp = rem % NSLICE;
    int qc = dir, tc = 1 - dir;
    int tid = threadIdx.x;
    int home = qt >> 1;

    int pruned;
    if (sp == home) {
        pruned = 1;   // fully covered by seed
    } else {
        float4 p = g_pts[qc][qt * QPB2 + tid];
        float bnd = dec_f(g_best[dir][__float_as_int(p.w)]);
        float wlo = p.x, whi = p.x;
#pragma unroll
        for (int off = 16; off >= 1; off >>= 1) {
            bnd = fmaxf(bnd, __shfl_xor_sync(0xffffffffu, bnd, off));
            wlo = fminf(wlo, __shfl_xor_sync(0xffffffffu, wlo, off));
            whi = fmaxf(whi, __shfl_xor_sync(0xffffffffu, whi, off));
        }
        float slo = dec_f(g_exlo[tc][sp]), shi = dec_f(g_exhi[tc][sp]);
        float gap = fmaxf(0.f, fmaxf(slo - whi, wlo - shi));
        pruned = (gap * gap > bnd + 1e-3f);
    }
    if (__syncthreads_and(pruned)) return;

    {
        int tb = sp * SLICEN;
        for (int k = tid; k < SLICEN * 2; k += TPBS) sB4[k] = g_frag[tc][tb + (k >> 1)][k & 1];
    }
    __syncthreads();
    if (pruned) return;

    sweep_and_commit(reinterpret_cast<const uint2*>(sB4), SLICEN,
                     qc, dir, qt * QPB2, tid);
}

// ============================================================================
// 6) fused reduction: block partial sums + last-block-ticket final sum.
// ============================================================================
__global__ void __launch_bounds__(TPB)
k_red(float* __restrict__ out) {
    __shared__ float sh[TPB];
    __shared__ int   amLast;
    int rid = blockIdx.x * TPB + threadIdx.x;
    int dir = rid >> 14, row = rid & (NPTS - 1);
    sh[threadIdx.x] = dec_f(g_best[dir][row]);
    __syncthreads();
    for (int k = TPB / 2; k > 0; k >>= 1) {
        if (threadIdx.x < k) sh[threadIdx.x] += sh[threadIdx.x + k];
        __syncthreads();
    }
    if (threadIdx.x == 0) {
        g_bsum[blockIdx.x] = sh[0];
        __threadfence();
        amLast = (atomicAdd(&g_ticket, 1u) == REDB - 1);
    }
    __syncthreads();
    if (amLast && threadIdx.x == 0) {
        float s = 0.f;
#pragma unroll
        for (int k = 0; k < REDB; k++) s += *((volatile float*)&g_bsum[k]);
        out[0] = s / (float)NPTS;
        g_ticket = 0;   // replay reset
    }
}

extern "C" void kernel_launch(void* const* d_in, const int* in_sizes, int n_in,
                              void* d_out, int out_size) {
    const float* adv = (const float*)d_in[0];
    const float* ori = (const float*)d_in[1];
    k_hist<<<2 * NPTS / 256, 256>>>(adv, ori);
    k_scan<<<1, 64>>>();
    k_scatter<<<2 * NPTS / 256, 256>>>(adv, ori);
    k_seed<<<2 * QT2 * SQUART, TPBS>>>();
    k_sweep<<<2 * QT2 * NSLICE, TPBS>>>();
    k_red<<<REDB, TPB>>>((float*)d_out);
}

// round 16
// speedup vs baseline: 1.0728x; 1.0728x over previous
#include <cuda_runtime.h>
#include <cuda_fp16.h>
#include <cstdint>

#define NPTS    16384
#define NBINS   256
#define NSLICE  16
#define SLICEN  (NPTS/NSLICE)      // 1024 targets per slice
#define SQUART  8                  // seed units per home slice (occupancy lever)
#define SEEDN   (SLICEN/SQUART)    // 128 targets per seed unit
#define TPB     256
#define QPB     256                // queries per tile
#define QT      (NPTS/QPB)         // 64 tiles per direction
#define REDB    (2*NPTS/TPB)       // 128 reduction blocks
#define XLO     (-8.0f)
#define XWIDTH  (16.0f/NBINS)

// ---- pipeline state; everything transient is re-initialized each replay ----
__device__ int      g_hist[2][NBINS];
__device__ int      g_start[2][NBINS + 1];
__device__ int      g_cursor[2][NBINS];
__device__ unsigned g_exlo[2][NSLICE], g_exhi[2][NSLICE]; // encoded slice x-ranges
__device__ float4   g_pts[2][NPTS];          // sorted (x,y,z, orig_idx bits)
__device__ uint4    g_frag[2][NPTS][2];      // target B-fragments, sorted order
__device__ unsigned g_best[2][NPTS];         // per-row best dist (encoded), atomicMin
__device__ float    g_bsum[REDB];
__device__ unsigned g_ticket;

// ---- order-preserving float<->uint encode ----
static __device__ __forceinline__ unsigned enc_f(float f) {
    unsigned u = __float_as_uint(f);
    return (u & 0x80000000u) ? ~u : (u | 0x80000000u);
}
static __device__ __forceinline__ float dec_f(unsigned u) {
    unsigned b = (u & 0x80000000u) ? (u & 0x7fffffffu) : ~u;
    return __uint_as_float(b);
}
static __device__ __forceinline__ unsigned pkh2(__half lo, __half hi) {
    __half2 h = __halves2half2(lo, hi);
    return *reinterpret_cast<unsigned*>(&h);
}

// m16n8k16 fp16 MMA, fp32 accumulate. A row-major, B col-major.
#define MMA_F16(d0,d1,d2,d3, a0,a1,a2,a3, b0,b1, c0,c1,c2,c3)                       \
    asm("mma.sync.aligned.m16n8k16.row.col.f32.f16.f16.f32 "                        \
        "{%0,%1,%2,%3}, {%4,%5,%6,%7}, {%8,%9}, {%10,%11,%12,%13};"                 \
        : "=f"(d0), "=f"(d1), "=f"(d2), "=f"(d3)                                    \
        : "r"(a0), "r"(a1), "r"(a2), "r"(a3), "r"(b0), "r"(b1),                     \
          "f"(c0), "f"(c1), "f"(c2), "f"(c3))

// ============================================================================
// 1) x-histogram + per-row best init (each (dir,row) touched exactly once)
// ============================================================================
__global__ void k_hist(const float* __restrict__ adv, const float* __restrict__ ori) {
    int i = blockIdx.x * blockDim.x + threadIdx.x;
    int c = i >> 14, idx = i & (NPTS - 1);
    const float* src = c ? ori : adv;
    float x = src[3 * idx];
    int bin = min(max((int)((x - XLO) * (1.0f / XWIDTH)), 0), NBINS - 1);
    atomicAdd(&g_hist[c][bin], 1);
    g_best[c][idx] = 0xFF800000u;   // enc(+inf)
}

// ============================================================================
// 2) prefix-sum; zero hist/cursor; init slice-range accumulators. 1 blk, 2 warps.
// ============================================================================
__global__ void k_scan() {
    int lane = threadIdx.x & 31;
    int c    = threadIdx.x >> 5;
    int h[8], s8 = 0;
#pragma unroll
    for (int k = 0; k < 8; k++) { h[k] = g_hist[c][lane * 8 + k]; s8 += h[k]; }
    int incl = s8;
#pragma unroll
    for (int off = 1; off < 32; off <<= 1) {
        int v = __shfl_up_sync(0xffffffffu, incl, off);
        if (lane >= off) incl += v;
    }
    int run = incl - s8;
#pragma unroll
    for (int k = 0; k < 8; k++) { g_start[c][lane * 8 + k] = run; run += h[k]; }
    if (lane == 31) g_start[c][NBINS] = run;
#pragma unroll
    for (int k = 0; k < 8; k++) {
        g_hist[c][lane * 8 + k]   = 0;
        g_cursor[c][lane * 8 + k] = 0;
    }
    if (lane < NSLICE) { g_exlo[c][lane] = 0xFFFFFFFFu; g_exhi[c][lane] = 0u; }
}

// ============================================================================
// 3) counting-sort scatter: sorted points + fp16-split B fragments + exact
//    slice x-ranges via encoded min/max atomics.
// ============================================================================
__global__ void k_scatter(const float* __restrict__ adv, const float* __restrict__ ori) {
    int i = blockIdx.x * blockDim.x + threadIdx.x;
    int c = i >> 14, idx = i & (NPTS - 1);
    const float* src = c ? ori : adv;
    float x = src[3 * idx], y = src[3 * idx + 1], z = src[3 * idx + 2];
    int bin = min(max((int)((x - XLO) * (1.0f / XWIDTH)), 0), NBINS - 1);
    int pos = g_start[c][bin] + atomicAdd(&g_cursor[c][bin], 1);

    g_pts[c][pos] = make_float4(x, y, z, __int_as_float(idx));
    int s = pos >> 10;              // pos / SLICEN
    unsigned ex = enc_f(x);
    atomicMin(&g_exlo[c][s], ex);
    atomicMax(&g_exhi[c][s], ex);

    __half xh = __float2half_rn(x), yh = __float2half_rn(y), zh = __float2half_rn(z);
    __half xl = __float2half_rn(x - __half2float(xh));
    __half yl = __float2half_rn(y - __half2float(yh));
    __half zl = __float2half_rn(z - __half2float(zh));
    float tq = -0.5f * (x * x + y * y + z * z);
    __half tqh = __float2half_rn(tq);
    __half tql = __float2half_rn(tq - __half2float(tqh));
    __half hz  = __float2half_rn(0.f);
    unsigned Q0 = pkh2(xh, yh), Q1 = pkh2(zh, xh), Q2 = pkh2(yh, zh);
    unsigned Q3 = pkh2(xl, yl), Q4 = pkh2(zl, tqh), Q5 = pkh2(tql, hz);
    g_frag[c][pos][0] = make_uint4(Q0, Q4, Q1, Q5);
    g_frag[c][pos][1] = make_uint4(Q2, 0u, Q3, 0u);
}

// ---- stage one query's fragments into smem (point already loaded) ----
static __device__ __forceinline__ void stage_query_p(
    float4 p, int tid, unsigned (*qA)[8], float* sQsq, int* sQid) {
    float x = p.x, y = p.y, z = p.z;
    __half xh = __float2half_rn(x), yh = __float2half_rn(y), zh = __float2half_rn(z);
    __half xl = __float2half_rn(x - __half2float(xh));
    __half yl = __float2half_rn(y - __half2float(yh));
    __half zl = __float2half_rn(z - __half2float(zh));
    __half one = __float2half_rn(1.f), hz = __float2half_rn(0.f);
    qA[tid][0] = pkh2(xh, yh);  qA[tid][1] = pkh2(zh, one);
    qA[tid][2] = pkh2(zh, xl);  qA[tid][3] = pkh2(one, hz);
    qA[tid][4] = pkh2(yl, zl);  qA[tid][5] = 0u;
    qA[tid][6] = pkh2(xh, yh);  qA[tid][7] = 0u;
    sQsq[tid] = x * x + y * y + z * z;
    sQid[tid] = __float_as_int(p.w);
}

// ---- the shared MMA inner sweep over TN targets from smem ----
static __device__ __forceinline__ void mma_sweep(
    const uint2* sb, int TN, unsigned a00, unsigned a01, unsigned a02, unsigned a03,
    unsigned a10, unsigned a11, unsigned a12, unsigned a13, int gid, int tl,
    float& mx00, float& mx01, float& mx10, float& mx11) {
    const float zf = 0.0f;
#pragma unroll 4
    for (int j = 0; j < TN; j += 8) {
        uint2 bb = sb[(j + gid) * 4 + tl];
        float d0, d1, d2, d3;
        MMA_F16(d0, d1, d2, d3, a00, a01, a02, a03, bb.x, bb.y, zf, zf, zf, zf);
        mx00 = fmaxf(mx00, fmaxf(d0, d1));
        mx01 = fmaxf(mx01, fmaxf(d2, d3));
        MMA_F16(d0, d1, d2, d3, a10, a11, a12, a13, bb.x, bb.y, zf, zf, zf, zf);
        mx10 = fmaxf(mx10, fmaxf(d0, d1));
        mx11 = fmaxf(mx11, fmaxf(d2, d3));
    }
}

// ============================================================================
// 4) seed: block = (dir, qt, eighth of home slice). Grid 1024 -> ~55 warps/SM.
//    atomicMin per-row best; union over the 8 units = tight home-slice bound.
// ============================================================================
__global__ void __launch_bounds__(TPB)
k_seed() {
    __shared__ uint4    sB4[SEEDN * 2];    // 4 KB
    __shared__ unsigned qA[QPB][8];        // 8 KB
    __shared__ float    sQsq[QPB];
    __shared__ int      sQid[QPB];

    int b = blockIdx.x;
    int dir = b / (QT * SQUART);
    int rem = b % (QT * SQUART);
    int qt = rem / SQUART, qu = rem % SQUART;
    int qc = dir, tc = 1 - dir;
    int tid = threadIdx.x;
    int tb = (qt >> 2) * SLICEN + qu * SEEDN;

    stage_query_p(g_pts[qc][qt * QPB + tid], tid, qA, sQsq, sQid);
    for (int k = tid; k < SEEDN * 2; k += TPB) sB4[k] = g_frag[tc][tb + (k >> 1)][k & 1];
    __syncthreads();

    int lane = tid & 31, warp = tid >> 5;
    int gid = lane >> 2, tl = lane & 3;
    int lr = warp * 32 + gid;

    uint2 u0 = *reinterpret_cast<const uint2*>(&qA[lr +  0][2 * tl]);
    uint2 u1 = *reinterpret_cast<const uint2*>(&qA[lr +  8][2 * tl]);
    uint2 u2 = *reinterpret_cast<const uint2*>(&qA[lr + 16][2 * tl]);
    uint2 u3 = *reinterpret_cast<const uint2*>(&qA[lr + 24][2 * tl]);

    float ninf = __int_as_float(0xFF800000);
    float mx00 = ninf, mx01 = ninf, mx10 = ninf, mx11 = ninf;
    mma_sweep(reinterpret_cast<const uint2*>(sB4), SEEDN,
              u0.x, u1.x, u0.y, u1.y, u2.x, u3.x, u2.y, u3.y, gid, tl,
              mx00, mx01, mx10, mx11);

#pragma unroll
    for (int off = 1; off <= 2; off <<= 1) {
        mx00 = fmaxf(mx00, __shfl_xor_sync(0xffffffffu, mx00, off));
        mx01 = fmaxf(mx01, __shfl_xor_sync(0xffffffffu, mx01, off));
        mx10 = fmaxf(mx10, __shfl_xor_sync(0xffffffffu, mx10, off));
        mx11 = fmaxf(mx11, __shfl_xor_sync(0xffffffffu, mx11, off));
    }
    if (tl == 0) {
        atomicMin(&g_best[dir][sQid[lr +  0]], enc_f(fmaf(-2.f, mx00, sQsq[lr +  0])));
        atomicMin(&g_best[dir][sQid[lr +  8]], enc_f(fmaf(-2.f, mx01, sQsq[lr +  8])));
        atomicMin(&g_best[dir][sQid[lr + 16]], enc_f(fmaf(-2.f, mx10, sQsq[lr + 16])));
        atomicMin(&g_best[dir][sQid[lr + 24]], enc_f(fmaf(-2.f, mx11, sQsq[lr + 24])));
    }
}

// ============================================================================
// 5) sweep: block = (dir, qt, sp). Per-warp TIGHT bound from g_best in the
//    prologue; prune via x-gap. Survivors cooperatively stage the 32KB B tile.
// ============================================================================
__global__ void __launch_bounds__(TPB)
k_sweep() {
    __shared__ uint4    sB4[SLICEN * 2];   // 32 KB
    __shared__ unsigned qA[QPB][8];
    __shared__ float    sQsq[QPB];
    __shared__ int      sQid[QPB];

    int b = blockIdx.x;
    int dir = b / (QT * NSLICE);
    int rem = b % (QT * NSLICE);
    int qt = rem / NSLICE, sp = rem % NSLICE;
    int qc = dir, tc = 1 - dir;
    int tid = threadIdx.x;
    int warp = tid >> 5, lane = tid & 31;
    int home = qt >> 2;

    float4 p = g_pts[qc][qt * QPB + tid];
    int pruned;
    if (sp == home) {
        pruned = 1;   // covered by seed
    } else {
        float bnd = dec_f(g_best[dir][__float_as_int(p.w)]);
        float wlo = p.x, whi = p.x;
#pragma unroll
        for (int off = 16; off >= 1; off >>= 1) {
            bnd = fmaxf(bnd, __shfl_xor_sync(0xffffffffu, bnd, off));
            wlo = fminf(wlo, __shfl_xor_sync(0xffffffffu, wlo, off));
            whi = fmaxf(whi, __shfl_xor_sync(0xffffffffu, whi, off));
        }
        float slo = dec_f(g_exlo[tc][sp]), shi = dec_f(g_exhi[tc][sp]);
        float gap = fmaxf(0.f, fmaxf(slo - whi, wlo - shi));
        pruned = (gap * gap > bnd + 1e-3f);
    }
    if (__syncthreads_and(pruned)) return;

    stage_query_p(p, tid, qA, sQsq, sQid);
    {
        int tb = sp * SLICEN;
        for (int k = tid; k < SLICEN * 2; k += TPB) sB4[k] = g_frag[tc][tb + (k >> 1)][k & 1];
    }
    __syncthreads();
    if (pruned) return;

    int gid = lane >> 2, tl = lane & 3;
    int lr = warp * 32 + gid;
    uint2 u0 = *reinterpret_cast<const uint2*>(&qA[lr +  0][2 * tl]);
    uint2 u1 = *reinterpret_cast<const uint2*>(&qA[lr +  8][2 * tl]);
    uint2 u2 = *reinterpret_cast<const uint2*>(&qA[lr + 16][2 * tl]);
    uint2 u3 = *reinterpret_cast<const uint2*>(&qA[lr + 24][2 * tl]);

    float ninf = __int_as_float(0xFF800000);
    float mx00 = ninf, mx01 = ninf, mx10 = ninf, mx11 = ninf;
    mma_sweep(reinterpret_cast<const uint2*>(sB4), SLICEN,
              u0.x, u1.x, u0.y, u1.y, u2.x, u3.x, u2.y, u3.y, gid, tl,
              mx00, mx01, mx10, mx11);

#pragma unroll
    for (int off = 1; off <= 2; off <<= 1) {
        mx00 = fmaxf(mx00, __shfl_xor_sync(0xffffffffu, mx00, off));
        mx01 = fmaxf(mx01, __shfl_xor_sync(0xffffffffu, mx01, off));
        mx10 = fmaxf(mx10, __shfl_xor_sync(0xffffffffu, mx10, off));
        mx11 = fmaxf(mx11, __shfl_xor_sync(0xffffffffu, mx11, off));
    }
    if (tl == 0) {
        atomicMin(&g_best[dir][sQid[lr +  0]], enc_f(fmaf(-2.f, mx00, sQsq[lr +  0])));
        atomicMin(&g_best[dir][sQid[lr +  8]], enc_f(fmaf(-2.f, mx01, sQsq[lr +  8])));
        atomicMin(&g_best[dir][sQid[lr + 16]], enc_f(fmaf(-2.f, mx10, sQsq[lr + 16])));
        atomicMin(&g_best[dir][sQid[lr + 24]], enc_f(fmaf(-2.f, mx11, sQsq[lr + 24])));
    }
}

// ============================================================================
// 6) fused reduction: block partial sums + last-block-ticket final sum.
// ============================================================================
__global__ void __launch_bounds__(TPB)
k_red(float* __restrict__ out) {
    __shared__ float sh[TPB];
    __shared__ int   amLast;
    int rid = blockIdx.x * TPB + threadIdx.x;
    int dir = rid >> 14, row = rid & (NPTS - 1);
    sh[threadIdx.x] = dec_f(g_best[dir][row]);
    __syncthreads();
    for (int k = TPB / 2; k > 0; k >>= 1) {
        if (threadIdx.x < k) sh[threadIdx.x] += sh[threadIdx.x + k];
        __syncthreads();
    }
    if (threadIdx.x == 0) {
        g_bsum[blockIdx.x] = sh[0];
        __threadfence();
        amLast = (atomicAdd(&g_ticket, 1u) == REDB - 1);
    }
    __syncthreads();
    if (amLast && threadIdx.x == 0) {
        float s = 0.f;
#pragma unroll
        for (int k = 0; k < REDB; k++) s += *((volatile float*)&g_bsum[k]);
        out[0] = s / (float)NPTS;
        g_ticket = 0;   // reset for next graph replay
    }
}

extern "C" void kernel_launch(void* const* d_in, const int* in_sizes, int n_in,
                              void* d_out, int out_size) {
    const float* adv = (const float*)d_in[0];
    const float* ori = (const float*)d_in[1];
    k_hist<<<2 * NPTS / 256, 256>>>(adv, ori);
    k_scan<<<1, 64>>>();
    k_scatter<<<2 * NPTS / 256, 256>>>(adv, ori);
    k_seed<<<2 * QT * SQUART, TPB>>>();
    k_sweep<<<2 * QT * NSLICE, TPB>>>();
    k_red<<<REDB, TPB>>>((float*)d_out);
}

// round 17
// speedup vs baseline: 1.1311x; 1.0543x over previous
#include <cuda_runtime.h>
#include <cuda_fp16.h>
#include <cstdint>

#define NPTS    16384
#define NBINS   256
#define NSLICE  16
#define SLICEN  (NPTS/NSLICE)      // 1024 targets per slice
#define SQUART  8                  // seed units per home slice
#define SEEDN   (SLICEN/SQUART)    // 128 targets per seed unit
#define TPB     256
#define QPB     256                // queries per tile
#define QT      (NPTS/QPB)         // 64 tiles per direction
#define REDB    (2*NPTS/TPB)       // 128 reduction blocks
#define XLO     (-8.0f)
#define XWIDTH  (16.0f/NBINS)

// ---- pipeline state; everything transient is re-initialized each replay ----
__device__ int      g_hist[2][NBINS];
__device__ int      g_start[2][NBINS + 1];
__device__ int      g_cursor[2][NBINS];
__device__ unsigned g_exlo[2][NSLICE], g_exhi[2][NSLICE]; // encoded slice x-ranges
__device__ float4   g_pts[2][NPTS];          // sorted (x,y,z, orig_idx bits)
__device__ uint4    g_frag[2][NPTS][2];      // target B-fragments, sorted order
__device__ unsigned g_best[2][NPTS];         // per-row best, SORTED-POSITION indexed
__device__ float    g_bsum[REDB];
__device__ unsigned g_ticket;

// ---- order-preserving float<->uint encode ----
static __device__ __forceinline__ unsigned enc_f(float f) {
    unsigned u = __float_as_uint(f);
    return (u & 0x80000000u) ? ~u : (u | 0x80000000u);
}
static __device__ __forceinline__ float dec_f(unsigned u) {
    unsigned b = (u & 0x80000000u) ? (u & 0x7fffffffu) : ~u;
    return __uint_as_float(b);
}
static __device__ __forceinline__ unsigned pkh2(__half lo, __half hi) {
    __half2 h = __halves2half2(lo, hi);
    return *reinterpret_cast<unsigned*>(&h);
}

// m16n8k16 fp16 MMA, fp32 accumulate. A row-major, B col-major.
#define MMA_F16(d0,d1,d2,d3, a0,a1,a2,a3, b0,b1, c0,c1,c2,c3)                       \
    asm("mma.sync.aligned.m16n8k16.row.col.f32.f16.f16.f32 "                        \
        "{%0,%1,%2,%3}, {%4,%5,%6,%7}, {%8,%9}, {%10,%11,%12,%13};"                 \
        : "=f"(d0), "=f"(d1), "=f"(d2), "=f"(d3)                                    \
        : "r"(a0), "r"(a1), "r"(a2), "r"(a3), "r"(b0), "r"(b1),                     \
          "f"(c0), "f"(c1), "f"(c2), "f"(c3))

// ============================================================================
// 1) x-histogram + per-row best init
// ============================================================================
__global__ void k_hist(const float* __restrict__ adv, const float* __restrict__ ori) {
    int i = blockIdx.x * blockDim.x + threadIdx.x;
    int c = i >> 14, idx = i & (NPTS - 1);
    const float* src = c ? ori : adv;
    float x = src[3 * idx];
    int bin = min(max((int)((x - XLO) * (1.0f / XWIDTH)), 0), NBINS - 1);
    atomicAdd(&g_hist[c][bin], 1);
    g_best[c][idx] = 0xFF800000u;   // enc(+inf)  (position-indexed; any cover works)
}

// ============================================================================
// 2) prefix-sum; zero hist/cursor; init slice-range accumulators. 1 blk, 2 warps.
// ============================================================================
__global__ void k_scan() {
    int lane = threadIdx.x & 31;
    int c    = threadIdx.x >> 5;
    int h[8], s8 = 0;
#pragma unroll
    for (int k = 0; k < 8; k++) { h[k] = g_hist[c][lane * 8 + k]; s8 += h[k]; }
    int incl = s8;
#pragma unroll
    for (int off = 1; off < 32; off <<= 1) {
        int v = __shfl_up_sync(0xffffffffu, incl, off);
        if (lane >= off) incl += v;
    }
    int run = incl - s8;
#pragma unroll
    for (int k = 0; k < 8; k++) { g_start[c][lane * 8 + k] = run; run += h[k]; }
    if (lane == 31) g_start[c][NBINS] = run;
#pragma unroll
    for (int k = 0; k < 8; k++) {
        g_hist[c][lane * 8 + k]   = 0;
        g_cursor[c][lane * 8 + k] = 0;
    }
    if (lane < NSLICE) { g_exlo[c][lane] = 0xFFFFFFFFu; g_exhi[c][lane] = 0u; }
}

// ============================================================================
// 3) counting-sort scatter: sorted points + fp16-split B fragments + exact
//    slice x-ranges via encoded min/max atomics.
// ============================================================================
__global__ void k_scatter(const float* __restrict__ adv, const float* __restrict__ ori) {
    int i = blockIdx.x * blockDim.x + threadIdx.x;
    int c = i >> 14, idx = i & (NPTS - 1);
    const float* src = c ? ori : adv;
    float x = src[3 * idx], y = src[3 * idx + 1], z = src[3 * idx + 2];
    int bin = min(max((int)((x - XLO) * (1.0f / XWIDTH)), 0), NBINS - 1);
    int pos = g_start[c][bin] + atomicAdd(&g_cursor[c][bin], 1);

    g_pts[c][pos] = make_float4(x, y, z, __int_as_float(idx));
    int s = pos >> 10;              // pos / SLICEN
    unsigned ex = enc_f(x);
    atomicMin(&g_exlo[c][s], ex);
    atomicMax(&g_exhi[c][s], ex);

    __half xh = __float2half_rn(x), yh = __float2half_rn(y), zh = __float2half_rn(z);
    __half xl = __float2half_rn(x - __half2float(xh));
    __half yl = __float2half_rn(y - __half2float(yh));
    __half zl = __float2half_rn(z - __half2float(zh));
    float tq = -0.5f * (x * x + y * y + z * z);
    __half tqh = __float2half_rn(tq);
    __half tql = __float2half_rn(tq - __half2float(tqh));
    __half hz  = __float2half_rn(0.f);
    unsigned Q0 = pkh2(xh, yh), Q1 = pkh2(zh, xh), Q2 = pkh2(yh, zh);
    unsigned Q3 = pkh2(xl, yl), Q4 = pkh2(zl, tqh), Q5 = pkh2(tql, hz);
    g_frag[c][pos][0] = make_uint4(Q0, Q4, Q1, Q5);
    g_frag[c][pos][1] = make_uint4(Q2, 0u, Q3, 0u);
}

// ---- stage one query's fragments into smem (point already loaded) ----
static __device__ __forceinline__ void stage_query_p(
    float4 p, int tid, unsigned (*qA)[8], float* sQsq) {
    float x = p.x, y = p.y, z = p.z;
    __half xh = __float2half_rn(x), yh = __float2half_rn(y), zh = __float2half_rn(z);
    __half xl = __float2half_rn(x - __half2float(xh));
    __half yl = __float2half_rn(y - __half2float(yh));
    __half zl = __float2half_rn(z - __half2float(zh));
    __half one = __float2half_rn(1.f), hz = __float2half_rn(0.f);
    qA[tid][0] = pkh2(xh, yh);  qA[tid][1] = pkh2(zh, one);
    qA[tid][2] = pkh2(zh, xl);  qA[tid][3] = pkh2(one, hz);
    qA[tid][4] = pkh2(yl, zl);  qA[tid][5] = 0u;
    qA[tid][6] = pkh2(xh, yh);  qA[tid][7] = 0u;
    sQsq[tid] = x * x + y * y + z * z;
}

// ---- the shared MMA inner sweep over TN targets from smem ----
static __device__ __forceinline__ void mma_sweep(
    const uint2* sb, int TN, unsigned a00, unsigned a01, unsigned a02, unsigned a03,
    unsigned a10, unsigned a11, unsigned a12, unsigned a13, int gid, int tl,
    float& mx00, float& mx01, float& mx10, float& mx11) {
    const float zf = 0.0f;
#pragma unroll 4
    for (int j = 0; j < TN; j += 8) {
        uint2 bb = sb[(j + gid) * 4 + tl];
        float d0, d1, d2, d3;
        MMA_F16(d0, d1, d2, d3, a00, a01, a02, a03, bb.x, bb.y, zf, zf, zf, zf);
        mx00 = fmaxf(mx00, fmaxf(d0, d1));
        mx01 = fmaxf(mx01, fmaxf(d2, d3));
        MMA_F16(d0, d1, d2, d3, a10, a11, a12, a13, bb.x, bb.y, zf, zf, zf, zf);
        mx10 = fmaxf(mx10, fmaxf(d0, d1));
        mx11 = fmaxf(mx11, fmaxf(d2, d3));
    }
}

// ---- fold 4 t-lanes per row + coalesced atomicMin at SORTED positions ----
static __device__ __forceinline__ void fold_commit(
    float mx00, float mx01, float mx10, float mx11,
    const float* sQsq, int dir, int qbase, int lr, int tl) {
#pragma unroll
    for (int off = 1; off <= 2; off <<= 1) {
        mx00 = fmaxf(mx00, __shfl_xor_sync(0xffffffffu, mx00, off));
        mx01 = fmaxf(mx01, __shfl_xor_sync(0xffffffffu, mx01, off));
        mx10 = fmaxf(mx10, __shfl_xor_sync(0xffffffffu, mx10, off));
        mx11 = fmaxf(mx11, __shfl_xor_sync(0xffffffffu, mx11, off));
    }
    if (tl == 0) {
        atomicMin(&g_best[dir][qbase + lr +  0], enc_f(fmaf(-2.f, mx00, sQsq[lr +  0])));
        atomicMin(&g_best[dir][qbase + lr +  8], enc_f(fmaf(-2.f, mx01, sQsq[lr +  8])));
        atomicMin(&g_best[dir][qbase + lr + 16], enc_f(fmaf(-2.f, mx10, sQsq[lr + 16])));
        atomicMin(&g_best[dir][qbase + lr + 24], enc_f(fmaf(-2.f, mx11, sQsq[lr + 24])));
    }
}

// ============================================================================
// 4) seed: block = (dir, qt, eighth of home slice). Grid 1024.
// ============================================================================
__global__ void __launch_bounds__(TPB)
k_seed() {
    __shared__ uint4    sB4[SEEDN * 2];    // 4 KB
    __shared__ unsigned qA[QPB][8];        // 8 KB
    __shared__ float    sQsq[QPB];

    int b = blockIdx.x;
    int dir = b / (QT * SQUART);
    int rem = b % (QT * SQUART);
    int qt = rem / SQUART, qu = rem % SQUART;
    int qc = dir, tc = 1 - dir;
    int tid = threadIdx.x;
    int tb = (qt >> 2) * SLICEN + qu * SEEDN;

    stage_query_p(g_pts[qc][qt * QPB + tid], tid, qA, sQsq);
    for (int k = tid; k < SEEDN * 2; k += TPB) sB4[k] = g_frag[tc][tb + (k >> 1)][k & 1];
    __syncthreads();

    int lane = tid & 31, warp = tid >> 5;
    int gid = lane >> 2, tl = lane & 3;
    int lr = warp * 32 + gid;

    uint2 u0 = *reinterpret_cast<const uint2*>(&qA[lr +  0][2 * tl]);
    uint2 u1 = *reinterpret_cast<const uint2*>(&qA[lr +  8][2 * tl]);
    uint2 u2 = *reinterpret_cast<const uint2*>(&qA[lr + 16][2 * tl]);
    uint2 u3 = *reinterpret_cast<const uint2*>(&qA[lr + 24][2 * tl]);

    float ninf = __int_as_float(0xFF800000);
    float mx00 = ninf, mx01 = ninf, mx10 = ninf, mx11 = ninf;
    mma_sweep(reinterpret_cast<const uint2*>(sB4), SEEDN,
              u0.x, u1.x, u0.y, u1.y, u2.x, u3.x, u2.y, u3.y, gid, tl,
              mx00, mx01, mx10, mx11);
    fold_commit(mx00, mx01, mx10, mx11, sQsq, dir, qt * QPB, lr, tl);
}

// ============================================================================
// 5) sweep: block = (dir, qt, sp). Per-warp tight bound via COALESCED g_best
//    load (sorted-position index); prune via x-gap.
// ============================================================================
__global__ void __launch_bounds__(TPB)
k_sweep() {
    __shared__ uint4    sB4[SLICEN * 2];   // 32 KB
    __shared__ unsigned qA[QPB][8];
    __shared__ float    sQsq[QPB];

    int b = blockIdx.x;
    int dir = b / (QT * NSLICE);
    int rem = b % (QT * NSLICE);
    int qt = rem / NSLICE, sp = rem % NSLICE;
    int qc = dir, tc = 1 - dir;
    int tid = threadIdx.x;
    int warp = tid >> 5, lane = tid & 31;
    int home = qt >> 2;

    float4 p = g_pts[qc][qt * QPB + tid];
    int pruned;
    if (sp == home) {
        pruned = 1;   // covered by seed
    } else {
        float bnd = dec_f(g_best[dir][qt * QPB + tid]);   // coalesced
        float wlo = p.x, whi = p.x;
#pragma unroll
        for (int off = 16; off >= 1; off >>= 1) {
            bnd = fmaxf(bnd, __shfl_xor_sync(0xffffffffu, bnd, off));
            wlo = fminf(wlo, __shfl_xor_sync(0xffffffffu, wlo, off));
            whi = fmaxf(whi, __shfl_xor_sync(0xffffffffu, whi, off));
        }
        float slo = dec_f(g_exlo[tc][sp]), shi = dec_f(g_exhi[tc][sp]);
        float gap = fmaxf(0.f, fmaxf(slo - whi, wlo - shi));
        pruned = (gap * gap > bnd + 1e-3f);
    }
    if (__syncthreads_and(pruned)) return;

    stage_query_p(p, tid, qA, sQsq);
    {
        int tb = sp * SLICEN;
        for (int k = tid; k < SLICEN * 2; k += TPB) sB4[k] = g_frag[tc][tb + (k >> 1)][k & 1];
    }
    __syncthreads();
    if (pruned) return;

    int gid = lane >> 2, tl = lane & 3;
    int lr = warp * 32 + gid;
    uint2 u0 = *reinterpret_cast<const uint2*>(&qA[lr +  0][2 * tl]);
    uint2 u1 = *reinterpret_cast<const uint2*>(&qA[lr +  8][2 * tl]);
    uint2 u2 = *reinterpret_cast<const uint2*>(&qA[lr + 16][2 * tl]);
    uint2 u3 = *reinterpret_cast<const uint2*>(&qA[lr + 24][2 * tl]);

    float ninf = __int_as_float(0xFF800000);
    float mx00 = ninf, mx01 = ninf, mx10 = ninf, mx11 = ninf;
    mma_sweep(reinterpret_cast<const uint2*>(sB4), SLICEN,
              u0.x, u1.x, u0.y, u1.y, u2.x, u3.x, u2.y, u3.y, gid, tl,
              mx00, mx01, mx10, mx11);
    fold_commit(mx00, mx01, mx10, mx11, sQsq, dir, qt * QPB, lr, tl);
}

// ============================================================================
// 6) fused reduction: block partial sums + last-block-ticket final sum.
// ============================================================================
__global__ void __launch_bounds__(TPB)
k_red(float* __restrict__ out) {
    __shared__ float sh[TPB];
    __shared__ int   amLast;
    int rid = blockIdx.x * TPB + threadIdx.x;
    int dir = rid >> 14, row = rid & (NPTS - 1);
    sh[threadIdx.x] = dec_f(g_best[dir][row]);
    __syncthreads();
    for (int k = TPB / 2; k > 0; k >>= 1) {
        if (threadIdx.x < k) sh[threadIdx.x] += sh[threadIdx.x + k];
        __syncthreads();
    }
    if (threadIdx.x == 0) {
        g_bsum[blockIdx.x] = sh[0];
        __threadfence();
        amLast = (atomicAdd(&g_ticket, 1u) == REDB - 1);
    }
    __syncthreads();
    if (amLast && threadIdx.x == 0) {
        float s = 0.f;
#pragma unroll
        for (int k = 0; k < REDB; k++) s += *((volatile float*)&g_bsum[k]);
        out[0] = s / (float)NPTS;
        g_ticket = 0;   // reset for next graph replay
    }
}

extern "C" void kernel_launch(void* const* d_in, const int* in_sizes, int n_in,
                              void* d_out, int out_size) {
    const float* adv = (const float*)d_in[0];
    const float* ori = (const float*)d_in[1];
    k_hist<<<2 * NPTS / 256, 256>>>(adv, ori);
    k_scan<<<1, 64>>>();
    k_scatter<<<2 * NPTS / 256, 256>>>(adv, ori);
    k_seed<<<2 * QT * SQUART, TPB>>>();
    k_sweep<<<2 * QT * NSLICE, TPB>>>();
    k_red<<<REDB, TPB>>>((float*)d_out);
}